// round 8
// baseline (speedup 1.0000x reference)
#include <cuda_runtime.h>
#include <cstdint>
#include <math.h>

// ---------------- problem constants ----------------
#define NTOK 4096
#define DDIM 2048
#define HDIM 1408
#define NE   16
#define NS   2
#define NSLOT 18
#define TOPK 2
#define TM 128
#define TN 128
#define KC 64
#define MAXROWS 18432
#define MAXTILESM 144
#define NBN1 11              // HDIM/128
#define NCH1 32              // DDIM/64
#define NBN2 16              // DDIM/128
#define NCH2 22              // HDIM/64
#define CHB 16384            // bytes per tiled chunk: hi 128x64 + lo 128x64
#define CHU4 1024            // uint4 per chunk

// smem: rows of 64 B + 16 pad = 80 B pitch (conflict-free for 16B ldmatrix phases)
#define PITCH 80
#define TILEB (128*PITCH)    // 10240
#define OFF_TOK 0
#define OFF_W   512
#define OFF_SA  1024
#define OFF_SB  1536
#define OFF_T   2048
#define AHOF(b) (OFF_T + (b)*4*TILEB)
#define ALOF(b) (AHOF(b) + TILEB)
#define BHOF(b) (AHOF(b) + 2*TILEB)
#define BLOF(b) (AHOF(b) + 3*TILEB)
#define SMEM_BYTES (OFF_T + 8*TILEB)   // 83968

// ---------------- device scratch ----------------
__device__ __align__(16) int8_t g_w1q[(size_t)NSLOT * NBN1 * NCH1 * CHB];  // 104MB
__device__ __align__(16) int8_t g_w2q[(size_t)NSLOT * NBN2 * NCH2 * CHB];  // 104MB
__device__ __align__(16) int8_t g_xq[(size_t)NTOK * NCH1 * 128];           // 16.8MB
__device__ __align__(16) int8_t g_hq[(size_t)MAXTILESM * NCH2 * CHB];      // 52MB
__device__ __align__(16) float  g_hidf[(size_t)MAXROWS * HDIM];            // 104MB
__device__ float g_w1s[NSLOT * HDIM];
__device__ float g_w2s[NSLOT * DDIM];
__device__ float g_xs[NTOK];
__device__ float g_hs[MAXROWS];
__device__ int   g_row_token[MAXROWS];
__device__ float g_row_w[MAXROWS];
__device__ int   g_tile_slot[MAXTILESM];
__device__ int   g_topk_i[NTOK * TOPK];
__device__ float g_topk_w[NTOK * TOPK];
__device__ int   g_counts[NE];
__device__ int   g_fill[NE];
__device__ int   g_offsets[NSLOT];
__device__ float g_psum[NE];
__device__ float g_lsum[NE];

// ---------------- helpers ----------------
__device__ __forceinline__ uint32_t smem_u32(const void* p) {
    uint32_t a;
    asm("{ .reg .u64 t; cvta.to.shared.u64 t, %1; cvt.u32.u64 %0, t; }"
        : "=r"(a) : "l"(p));
    return a;
}
__device__ __forceinline__ void ldsm4(uint32_t* r, uint32_t addr) {
    asm volatile("ldmatrix.sync.aligned.m8n8.x4.shared.b16 {%0,%1,%2,%3}, [%4];"
                 : "=r"(r[0]), "=r"(r[1]), "=r"(r[2]), "=r"(r[3]) : "r"(addr));
}
__device__ __forceinline__ void mma_s8(int* d, const uint32_t* a, const uint32_t* b) {
    asm volatile("mma.sync.aligned.m16n8k32.row.col.s32.s8.s8.s32 "
                 "{%0,%1,%2,%3}, {%4,%5,%6,%7}, {%8,%9}, {%0,%1,%2,%3};"
                 : "+r"(d[0]), "+r"(d[1]), "+r"(d[2]), "+r"(d[3])
                 : "r"(a[0]), "r"(a[1]), "r"(a[2]), "r"(a[3]), "r"(b[0]), "r"(b[1]));
}
// 2-level quantization: v ~= s*(h + l/256)
__device__ __forceinline__ void q2(float v, float inv_s, int8_t& h, int8_t& l) {
    float u = v * inv_s;
    float hf = rintf(u);
    if (hf > 127.f) hf = 127.f;
    if (hf < -127.f) hf = -127.f;
    float lf = rintf((u - hf) * 256.0f);
    if (lf > 127.f) lf = 127.f;
    if (lf < -127.f) lf = -127.f;
    h = (int8_t)(int)hf;
    l = (int8_t)(int)lf;
}

// ---------------- init ----------------
__global__ void init_kernel(float* __restrict__ out) {
    int idx = blockIdx.x * blockDim.x + threadIdx.x;
    int stride = gridDim.x * blockDim.x;
    for (size_t i = idx; i < (size_t)NTOK * DDIM; i += stride) out[i] = 0.0f;
    for (int i = idx; i < MAXROWS; i += stride) g_row_token[i] = -1;
    if (idx < NE) {
        g_counts[idx] = 0; g_fill[idx] = 0;
        g_psum[idx] = 0.0f; g_lsum[idx] = 0.0f;
    }
}

// ---------------- router ----------------
__global__ void router_kernel(const float* __restrict__ x,
                              const float* __restrict__ gw) {
    int t = blockIdx.x;
    int tid = threadIdx.x;
    float acc[NE];
#pragma unroll
    for (int e = 0; e < NE; e++) acc[e] = 0.0f;
    const float* xr = x + (size_t)t * DDIM;
    for (int d = tid; d < DDIM; d += 128) {
        float xv = xr[d];
        const float* g = gw + d * NE;
#pragma unroll
        for (int e = 0; e < NE; e++) acc[e] += xv * g[e];
    }
    __shared__ float red[128][NE + 1];
#pragma unroll
    for (int e = 0; e < NE; e++) red[tid][e] = acc[e];
    __syncthreads();
    for (int off = 64; off > 0; off >>= 1) {
        if (tid < off) {
#pragma unroll
            for (int e = 0; e < NE; e++) red[tid][e] += red[tid + off][e];
        }
        __syncthreads();
    }
    if (tid == 0) {
        float lg[NE], p[NE];
        float m = -1e30f;
#pragma unroll
        for (int e = 0; e < NE; e++) { lg[e] = red[0][e]; m = fmaxf(m, lg[e]); }
        float s = 0.0f;
#pragma unroll
        for (int e = 0; e < NE; e++) { p[e] = expf(lg[e] - m); s += p[e]; }
        float inv = 1.0f / s;
#pragma unroll
        for (int e = 0; e < NE; e++) p[e] *= inv;
        int i1 = 0;
#pragma unroll
        for (int e = 1; e < NE; e++) if (p[e] > p[i1]) i1 = e;
        int i2 = (i1 == 0) ? 1 : 0;
#pragma unroll
        for (int e = 0; e < NE; e++) if (e != i1 && p[e] > p[i2]) i2 = e;
        float wsum = p[i1] + p[i2];
        g_topk_i[t * 2 + 0] = i1;
        g_topk_i[t * 2 + 1] = i2;
        g_topk_w[t * 2 + 0] = p[i1] / wsum;
        g_topk_w[t * 2 + 1] = p[i2] / wsum;
        atomicAdd(&g_counts[i1], 1);
        atomicAdd(&g_counts[i2], 1);
#pragma unroll
        for (int e = 0; e < NE; e++) {
            atomicAdd(&g_psum[e], p[e]);
            atomicAdd(&g_lsum[e], lg[e]);
        }
    }
}

// ---------------- schedule ----------------
__global__ void schedule_kernel(float* __restrict__ out, long long out_size) {
    if (threadIdx.x != 0 || blockIdx.x != 0) return;
    int tile = 0;
    for (int slot = 0; slot < NSLOT; slot++) {
        int cnt = (slot < NE) ? g_counts[slot] : NTOK;
        g_offsets[slot] = tile * TM;
        int nt = (cnt + TM - 1) / TM;
        for (int i = 0; i < nt; i++) g_tile_slot[tile++] = slot;
    }
    for (; tile < MAXTILESM; tile++) g_tile_slot[tile] = -1;
    float aux = 0.0f;
    for (int e = 0; e < NE; e++)
        aux += (g_psum[e] * (1.0f / NTOK)) * (g_lsum[e] * (1.0f / NTOK));
    aux *= (float)NE;
    if (out_size > (long long)NTOK * DDIM) out[(size_t)NTOK * DDIM] = aux;
}

// ---------------- scatter ----------------
__global__ void scatter_kernel() {
    int i = blockIdx.x * blockDim.x + threadIdx.x;
    const int total = NTOK * TOPK + NTOK * NS;
    if (i >= total) return;
    if (i < NTOK * TOPK) {
        int e = g_topk_i[i];
        int pos = atomicAdd(&g_fill[e], 1);
        int row = g_offsets[e] + pos;
        g_row_token[row] = i >> 1;
        g_row_w[row] = g_topk_w[i];
    } else {
        int j = i - NTOK * TOPK;
        int s = j / NTOK, t = j % NTOK;
        int row = g_offsets[NE + s] + t;
        g_row_token[row] = t;
        g_row_w[row] = 1.0f;
    }
}

// ---------------- weight scales: per (slot, n) max over K ----------------
template <int PH>
__global__ void wscale(const float* __restrict__ ew, const float* __restrict__ sw) {
    const int K = (PH == 1) ? DDIM : HDIM;
    const int N = (PH == 1) ? HDIM : DDIM;
    int n = blockIdx.x * 128 + threadIdx.x;
    int slot = blockIdx.y;
    if (n >= N) return;
    const float* src = (slot < NE) ? ew + (size_t)slot * K * N
                                   : sw + (size_t)(slot - NE) * K * N;
    float m = 0.0f;
#pragma unroll 4
    for (int k = 0; k < K; k++) m = fmaxf(m, fabsf(src[(size_t)k * N + n]));
    float s = fmaxf(m, 1e-30f) * (1.0f / 127.0f);
    if (PH == 1) g_w1s[slot * N + n] = s;
    else         g_w2s[slot * N + n] = s;
}

// ---------------- weight transpose + 2-level quant into tiled layout --------
template <int PH>
__global__ void wquant(const float* __restrict__ ew, const float* __restrict__ sw) {
    const int K = (PH == 1) ? DDIM : HDIM;
    const int N = (PH == 1) ? HDIM : DDIM;
    const int NBN = (PH == 1) ? NBN1 : NBN2;
    const int NCH = (PH == 1) ? NCH1 : NCH2;
    int8_t* dst = (PH == 1) ? g_w1q : g_w2q;
    const float* sarr = (PH == 1) ? g_w1s : g_w2s;
    int slot = blockIdx.z;
    const float* src = (slot < NE) ? ew + (size_t)slot * K * N
                                   : sw + (size_t)(slot - NE) * K * N;
    __shared__ float t[32][33];
    int k0 = blockIdx.x * 32, n0 = blockIdx.y * 32;
    int tx = threadIdx.x, ty = threadIdx.y;   // 32, 8
#pragma unroll
    for (int i = 0; i < 4; i++)
        t[ty + i * 8][tx] = src[(size_t)(k0 + ty + i * 8) * N + n0 + tx];
    __syncthreads();
    int k = k0 + tx;
#pragma unroll
    for (int i = 0; i < 4; i++) {
        int n = n0 + ty + i * 8;
        float v = t[tx][ty + i * 8];                 // src[k][n]
        float inv = 1.0f / sarr[slot * N + n];
        int8_t h, l; q2(v, inv, h, l);
        size_t base = ((size_t)(slot * NBN + (n >> 7)) * NCH + (k >> 6)) * CHB
                      + (size_t)(n & 127) * 64 + (k & 63);
        dst[base] = h;
        dst[base + 8192] = l;
    }
}

// ---------------- x quant: per-token scale, chunk-interleaved layout --------
__global__ void qx_kernel(const float* __restrict__ x) {
    int t = blockIdx.x;
    int tid = threadIdx.x;
    __shared__ float sx[DDIM];
    __shared__ float red[256];
    float m = 0.0f;
#pragma unroll
    for (int i = 0; i < DDIM / 1024; i++) {
        float4 v = *(const float4*)(x + (size_t)t * DDIM + (tid + i * 256) * 4);
        *(float4*)&sx[(tid + i * 256) * 4] = v;
        m = fmaxf(m, fmaxf(fmaxf(fabsf(v.x), fabsf(v.y)), fmaxf(fabsf(v.z), fabsf(v.w))));
    }
    red[tid] = m;
    __syncthreads();
    for (int off = 128; off > 0; off >>= 1) {
        if (tid < off) red[tid] = fmaxf(red[tid], red[tid + off]);
        __syncthreads();
    }
    float s = fmaxf(red[0], 1e-30f) * (1.0f / 127.0f);
    if (tid == 0) g_xs[t] = s;
    float inv = 1.0f / s;
    int8_t* dst = g_xq + (size_t)t * NCH1 * 128;
    for (int k = tid; k < DDIM; k += 256) {
        int8_t h, l; q2(sx[k], inv, h, l);
        int c = k >> 6, kk = k & 63;
        dst[c * 128 + kk] = h;
        dst[c * 128 + 64 + kk] = l;
    }
}

// ---------------- hidden quant: per-row scale, tiled layout -----------------
__global__ void qh_kernel() {
    int row = blockIdx.x;
    int tid = threadIdx.x;
    __shared__ float sx[HDIM];
    __shared__ float red[256];
    float m = 0.0f;
    for (int k = tid; k < HDIM; k += 256) {
        float v = g_hidf[(size_t)row * HDIM + k];
        sx[k] = v;
        m = fmaxf(m, fabsf(v));
    }
    red[tid] = m;
    __syncthreads();
    for (int off = 128; off > 0; off >>= 1) {
        if (tid < off) red[tid] = fmaxf(red[tid], red[tid + off]);
        __syncthreads();
    }
    float s = fmaxf(red[0], 1e-30f) * (1.0f / 127.0f);
    if (tid == 0) g_hs[row] = s;
    float inv = 1.0f / s;
    int8_t* dst = g_hq + (size_t)(row >> 7) * NCH2 * CHB;
    int r7 = row & 127;
    for (int k = tid; k < HDIM; k += 256) {
        int8_t h, l; q2(sx[k], inv, h, l);
        size_t base = (size_t)(k >> 6) * CHB + (size_t)r7 * 64 + (k & 63);
        dst[base] = h;
        dst[base + 8192] = l;
    }
}

// ------------- int8 2-level grouped FFN GEMM (m16n8k32, s32 accum) ----------
// PHASE1: hidf = silu(gather(x) @ W1)   K=DDIM -> fp32 g_hidf
// PHASE2: out += w_row * (hidden @ W2)  K=HDIM (atomicAdd)
template <bool PHASE1>
__global__ __launch_bounds__(512, 1)
void ffn_i8(float* __restrict__ out) {
    extern __shared__ char smem[];
    const int bm = blockIdx.x, bn = blockIdx.y;
    const int slot = g_tile_slot[bm];
    if (slot < 0) return;
    const int NC = PHASE1 ? NCH1 : NCH2;
    const int row0 = bm * TM, n0 = bn * TN;
    const int tid = threadIdx.x, wid = tid >> 5, lane = tid & 31;
    int* s_tok = (int*)(smem + OFF_TOK);
    float* s_w  = (float*)(smem + OFF_W);
    float* s_sa = (float*)(smem + OFF_SA);
    float* s_sb = (float*)(smem + OFF_SB);
    if (tid < TM) {
        int tok = g_row_token[row0 + tid];
        s_tok[tid] = tok;
        s_w[tid]   = g_row_w[row0 + tid];
        s_sa[tid]  = PHASE1 ? g_xs[tok < 0 ? 0 : tok] : g_hs[row0 + tid];
    } else if (tid < 2 * TM) {
        int i = tid - TM;
        s_sb[i] = PHASE1 ? g_w1s[slot * HDIM + n0 + i] : g_w2s[slot * DDIM + n0 + i];
    }
    __syncthreads();

    // ---- loader mapping ----
    // tiled block copy (B always; A in phase2): 1024 u4/chunk; thread t does u4[t](hi)+u4[t+512](lo)
    const int dT = (tid >> 2) * PITCH + (tid & 3) * 16;
    const uint4* srcB = PHASE1
        ? (const uint4*)g_w1q + (size_t)(slot * NBN1 + bn) * NCH1 * CHU4
        : (const uint4*)g_w2q + (size_t)(slot * NBN2 + bn) * NCH2 * CHU4;
    const uint4* srcA2 = 0;
    const int8_t* srcA1 = 0;
    const int xrow = tid >> 2, xpart = tid & 3;   // phase1 A mapping
    if (PHASE1) {
        int tok = s_tok[xrow]; if (tok < 0) tok = 0;
        srcA1 = g_xq + (size_t)tok * NCH1 * 128 + xpart * 32;
    } else {
        srcA2 = (const uint4*)g_hq + (size_t)bm * NCH2 * CHU4;
    }
    const int dA1 = xrow * PITCH + (xpart & 1) * 32;     // within hi or lo tile
    const bool a1hi = (xpart < 2);

    const uint32_t sb = smem_u32(smem);
    const int warp_m = (wid >> 2) * 32;
    const int warp_n = (wid & 3) * 32;
    // ldmatrix lane addressing
    const int a_row = (lane & 7) + ((lane >> 3) & 1) * 8;
    const int a_byte = (lane >> 4) * 16;
    const int b_row = (lane & 7) + ((lane >> 4) & 1) * 8;
    const int b_byte = ((lane >> 3) & 1) * 16;

    int hh[2][4][4], cc[2][4][4];
#pragma unroll
    for (int i = 0; i < 2; i++)
#pragma unroll
        for (int j = 0; j < 4; j++)
#pragma unroll
            for (int k = 0; k < 4; k++) { hh[i][j][k] = 0; cc[i][j][k] = 0; }

    // -------- direct load of chunk 0 --------
    {
        if (PHASE1) {
            const uint4* p = (const uint4*)srcA1;
            char* base = smem + (a1hi ? AHOF(0) : ALOF(0)) + dA1;
            *(uint4*)(base)      = p[0];
            *(uint4*)(base + 16) = p[1];
        } else {
            *(uint4*)(smem + AHOF(0) + dT) = srcA2[tid];
            *(uint4*)(smem + ALOF(0) + dT) = srcA2[tid + 512];
        }
        *(uint4*)(smem + BHOF(0) + dT) = srcB[tid];
        *(uint4*)(smem + BLOF(0) + dT) = srcB[tid + 512];
    }
    __syncthreads();

    // -------- main loop --------
    for (int c = 0; c < NC; c++) {
        const int buf = c & 1;
        const bool have = (c + 1 < NC);

        uint4 sA0, sA1v, sB0, sB1;
        if (have) {
            if (PHASE1) {
                const uint4* p = (const uint4*)(srcA1 + (size_t)(c + 1) * 128);
                sA0 = p[0]; sA1v = p[1];
            } else {
                const uint4* p = srcA2 + (size_t)(c + 1) * CHU4;
                sA0 = p[tid]; sA1v = p[tid + 512];
            }
            const uint4* q = srcB + (size_t)(c + 1) * CHU4;
            sB0 = q[tid]; sB1 = q[tid + 512];
        }

        // ---- compute ----
        {
            const uint32_t ahb = sb + AHOF(buf), alb = sb + ALOF(buf);
            const uint32_t bhb = sb + BHOF(buf), blb = sb + BLOF(buf);
#pragma unroll
            for (int kk = 0; kk < 64; kk += 32) {
                uint32_t bh[2][4], bl[2][4];
#pragma unroll
                for (int np = 0; np < 2; np++) {
                    uint32_t boff = (uint32_t)((warp_n + np * 16 + b_row) * PITCH + kk + b_byte);
                    ldsm4(bh[np], bhb + boff);
                    ldsm4(bl[np], blb + boff);
                }
#pragma unroll
                for (int mi = 0; mi < 2; mi++) {
                    uint32_t aoff = (uint32_t)((warp_m + mi * 16 + a_row) * PITCH + kk + a_byte);
                    uint32_t ah[4], al[4];
                    ldsm4(ah, ahb + aoff);
                    ldsm4(al, alb + aoff);
                    mma_s8(hh[mi][0], ah, &bh[0][0]);
                    mma_s8(hh[mi][1], ah, &bh[0][2]);
                    mma_s8(hh[mi][2], ah, &bh[1][0]);
                    mma_s8(hh[mi][3], ah, &bh[1][2]);
                    mma_s8(cc[mi][0], ah, &bl[0][0]);
                    mma_s8(cc[mi][1], ah, &bl[0][2]);
                    mma_s8(cc[mi][2], ah, &bl[1][0]);
                    mma_s8(cc[mi][3], ah, &bl[1][2]);
                    mma_s8(cc[mi][0], al, &bh[0][0]);
                    mma_s8(cc[mi][1], al, &bh[0][2]);
                    mma_s8(cc[mi][2], al, &bh[1][0]);
                    mma_s8(cc[mi][3], al, &bh[1][2]);
                }
            }
        }

        // ---- STS staged chunk ----
        if (have) {
            const int nb = (c + 1) & 1;
            if (PHASE1) {
                char* base = smem + (a1hi ? AHOF(nb) : ALOF(nb)) + dA1;
                *(uint4*)(base)      = sA0;
                *(uint4*)(base + 16) = sA1v;
            } else {
                *(uint4*)(smem + AHOF(nb) + dT) = sA0;
                *(uint4*)(smem + ALOF(nb) + dT) = sA1v;
            }
            *(uint4*)(smem + BHOF(nb) + dT) = sB0;
            *(uint4*)(smem + BLOF(nb) + dT) = sB1;
        }
        __syncthreads();
    }

    // -------- epilogue: combine scales --------
    const int gid = lane >> 2, tig = lane & 3;
#pragma unroll
    for (int mi = 0; mi < 2; mi++) {
#pragma unroll
        for (int nf = 0; nf < 4; nf++) {
            const int col = warp_n + nf * 8 + tig * 2;
            const float sb0 = s_sb[col], sb1 = s_sb[col + 1];
#pragma unroll
            for (int h = 0; h < 2; h++) {
                const int r = warp_m + mi * 16 + gid + h * 8;
                const float sa = s_sa[r];
                float e0 = (float)hh[mi][nf][2 * h]     + (float)cc[mi][nf][2 * h]     * (1.0f / 256.0f);
                float e1 = (float)hh[mi][nf][2 * h + 1] + (float)cc[mi][nf][2 * h + 1] * (1.0f / 256.0f);
                float v0 = sa * sb0 * e0;
                float v1 = sa * sb1 * e1;
                if (PHASE1) {
                    v0 = v0 / (1.0f + __expf(-v0));
                    v1 = v1 / (1.0f + __expf(-v1));
                    float2 p = make_float2(v0, v1);
                    *(float2*)(g_hidf + (size_t)(row0 + r) * HDIM + n0 + col) = p;
                } else {
                    int tok = s_tok[r];
                    if (tok >= 0) {
                        float w = s_w[r];
                        float* op = out + (size_t)tok * DDIM + n0 + col;
                        atomicAdd(op,     w * v0);
                        atomicAdd(op + 1, w * v1);
                    }
                }
            }
        }
    }
}

// ---------------- launch ----------------
extern "C" void kernel_launch(void* const* d_in, const int* in_sizes, int n_in,
                              void* d_out, int out_size) {
    const float* x   = (const float*)d_in[0];
    const float* gw  = (const float*)d_in[1];
    const float* sw1 = (const float*)d_in[2];
    const float* sw2 = (const float*)d_in[3];
    const float* ew1 = (const float*)d_in[4];
    const float* ew2 = (const float*)d_in[5];
    float* out = (float*)d_out;

    cudaFuncSetAttribute(ffn_i8<true>,  cudaFuncAttributeMaxDynamicSharedMemorySize, SMEM_BYTES);
    cudaFuncSetAttribute(ffn_i8<false>, cudaFuncAttributeMaxDynamicSharedMemorySize, SMEM_BYTES);

    init_kernel<<<1024, 256>>>(out);
    router_kernel<<<NTOK, 128>>>(x, gw);
    schedule_kernel<<<1, 32>>>(out, (long long)out_size);
    scatter_kernel<<<(NTOK * (TOPK + NS) + 255) / 256, 256>>>();

    wscale<1><<<dim3(NBN1, NSLOT), 128>>>(ew1, sw1);
    wscale<2><<<dim3(NBN2, NSLOT), 128>>>(ew2, sw2);
    dim3 tb(32, 8);
    wquant<1><<<dim3(DDIM / 32, HDIM / 32, NSLOT), tb>>>(ew1, sw1);
    wquant<2><<<dim3(HDIM / 32, DDIM / 32, NSLOT), tb>>>(ew2, sw2);
    qx_kernel<<<NTOK, 256>>>(x);

    ffn_i8<true ><<<dim3(MAXTILESM, NBN1), 512, SMEM_BYTES>>>(out);
    qh_kernel<<<MAXROWS, 256>>>();
    ffn_i8<false><<<dim3(MAXTILESM, NBN2), 512, SMEM_BYTES>>>(out);
}

// round 9
// speedup vs baseline: 1.5474x; 1.5474x over previous
#include <cuda_runtime.h>
#include <cuda_bf16.h>
#include <cstdint>
#include <math.h>

// ---------------- problem constants ----------------
#define NTOK 4096
#define DDIM 2048
#define HDIM 1408
#define NE   16
#define NS   2
#define NSLOT (NE + NS)
#define TOPK 2
#define TM 128
#define TN 128
#define KC 32
#define MAXROWS (NTOK*TOPK + NE*TM + NTOK*NS)   // 18432
#define MAXTILESM (MAXROWS / TM)                // 144
#define NBN1 (HDIM / TN)     // 11
#define NCH1 (DDIM / KC)     // 64
#define NBN2 (DDIM / TN)     // 16
#define NCH2 (HDIM / KC)     // 44
#define CHUNK_ELEM (2 * 128 * KC)   // 8192 elems (hi tile + lo tile)

// heterogeneous split: bn >= FP_SPLIT -> fp32 SIMT CTA (CUDA cores)
#define FP1_SPLIT 8          // phase1: 8 mma tiles, 3 fp32 tiles
#define FP2_SPLIT 12         // phase2: 12 mma tiles, 4 fp32 tiles

// smem tile geometry (mma path): rows of 32 bf16 + 8 pad = 80 bytes
#define PITCH 80
#define TILEB (128 * PITCH)          // 10240 B
#define OFF_TOK 0
#define OFF_W   512
#define OFF_TILES 1024
#define AHOF(b) (OFF_TILES + (b)*4*TILEB)
#define ALOF(b) (AHOF(b) + TILEB)
#define BHOF(b) (AHOF(b) + 2*TILEB)
#define BLOF(b) (AHOF(b) + 3*TILEB)
#define SMEM_BYTES (OFF_TILES + 8*TILEB)   // 82944
// fp32 path overlays As/Bs at OFF_TILES (16x132 floats each)
#define TKF 16

// ---------------- device scratch (tiled layouts) ----------------
__device__ __align__(16) __nv_bfloat16 g_w1t[(size_t)NSLOT * NBN1 * NCH1 * CHUNK_ELEM];
__device__ __align__(16) __nv_bfloat16 g_w2t[(size_t)NSLOT * NBN2 * NCH2 * CHUNK_ELEM];
__device__ __align__(16) __nv_bfloat16 g_xc[(size_t)NTOK * NCH1 * 64];
__device__ __align__(16) __nv_bfloat16 g_hid[(size_t)MAXTILESM * NCH2 * CHUNK_ELEM];
__device__ int   g_row_token[MAXROWS];
__device__ float g_row_w[MAXROWS];
__device__ int   g_tile_slot[MAXTILESM];
__device__ int   g_topk_i[NTOK * TOPK];
__device__ float g_topk_w[NTOK * TOPK];
__device__ int   g_counts[NE];
__device__ int   g_fill[NE];
__device__ int   g_offsets[NSLOT];
__device__ float g_psum[NE];
__device__ float g_lsum[NE];

// ---------------- helpers ----------------
__device__ __forceinline__ uint32_t smem_u32(const void* p) {
    uint32_t a;
    asm("{ .reg .u64 t; cvta.to.shared.u64 t, %1; cvt.u32.u64 %0, t; }"
        : "=r"(a) : "l"(p));
    return a;
}
__device__ __forceinline__ void ldsm4(uint32_t* r, uint32_t addr) {
    asm volatile("ldmatrix.sync.aligned.m8n8.x4.shared.b16 {%0,%1,%2,%3}, [%4];"
                 : "=r"(r[0]), "=r"(r[1]), "=r"(r[2]), "=r"(r[3]) : "r"(addr));
}
__device__ __forceinline__ void mma16816(float* d, const uint32_t* a, const uint32_t* b) {
    asm volatile("mma.sync.aligned.m16n8k16.row.col.f32.bf16.bf16.f32 "
                 "{%0,%1,%2,%3}, {%4,%5,%6,%7}, {%8,%9}, {%0,%1,%2,%3};"
                 : "+f"(d[0]), "+f"(d[1]), "+f"(d[2]), "+f"(d[3])
                 : "r"(a[0]), "r"(a[1]), "r"(a[2]), "r"(a[3]), "r"(b[0]), "r"(b[1]));
}
__device__ __forceinline__ uint32_t pk(__nv_bfloat16 a, __nv_bfloat16 b) {
    return (uint32_t)__bfloat16_as_ushort(a) | ((uint32_t)__bfloat16_as_ushort(b) << 16);
}
__device__ __forceinline__ void split_bf(float v, __nv_bfloat16& h, __nv_bfloat16& l) {
    h = __float2bfloat16_rn(v);
    l = __float2bfloat16_rn(v - __bfloat162float(h));
}
__device__ __forceinline__ void unpk2(uint32_t u, float& x, float& y) {
    x = __bfloat162float(__ushort_as_bfloat16((unsigned short)(u & 0xffff)));
    y = __bfloat162float(__ushort_as_bfloat16((unsigned short)(u >> 16)));
}

// ------- weight transpose+split into tiled layout ---------------------------
template <int PH>
__global__ void conv_w(const float* __restrict__ ew, const float* __restrict__ sw) {
    const int K = (PH == 1) ? DDIM : HDIM;
    const int N = (PH == 1) ? HDIM : DDIM;
    const int NBN = (PH == 1) ? NBN1 : NBN2;
    const int NCH = (PH == 1) ? NCH1 : NCH2;
    __nv_bfloat16* dst = (PH == 1) ? g_w1t : g_w2t;
    int slot = blockIdx.z;
    const float* src = (slot < NE) ? ew + (size_t)slot * K * N
                                   : sw + (size_t)(slot - NE) * K * N;
    __shared__ float t[32][33];
    int k0 = blockIdx.x * 32, n0 = blockIdx.y * 32;
    int tx = threadIdx.x, ty = threadIdx.y;   // 32, 8
#pragma unroll
    for (int i = 0; i < 4; i++)
        t[ty + i * 8][tx] = src[(size_t)(k0 + ty + i * 8) * N + n0 + tx];
    __syncthreads();
    const int c = k0 >> 5;
#pragma unroll
    for (int i = 0; i < 4; i++) {
        int n = n0 + ty + i * 8;
        float v = t[tx][ty + i * 8];
        __nv_bfloat16 h, l; split_bf(v, h, l);
        size_t base = ((size_t)(slot * NBN + (n >> 7)) * NCH + c) * CHUNK_ELEM
                      + (size_t)(n & 127) * KC + tx;
        dst[base] = h;
        dst[base + 128 * KC] = l;
    }
}

// ---------------- x split into chunk-interleaved layout ----------------
__global__ void conv_x(const float* __restrict__ x) {
    size_t i = ((size_t)blockIdx.x * blockDim.x + threadIdx.x) * 4;
    if (i >= (size_t)NTOK * DDIM) return;
    float4 v = *(const float4*)(x + i);
    __nv_bfloat16 h0, h1, h2, h3, l0, l1, l2, l3;
    split_bf(v.x, h0, l0); split_bf(v.y, h1, l1);
    split_bf(v.z, h2, l2); split_bf(v.w, h3, l3);
    int tok = (int)(i >> 11);
    int k = (int)(i & 2047);
    size_t base = ((size_t)tok * NCH1 + (k >> 5)) * 64 + (k & 31);
    *(uint2*)(g_xc + base)      = make_uint2(pk(h0, h1), pk(h2, h3));
    *(uint2*)(g_xc + base + 32) = make_uint2(pk(l0, l1), pk(l2, l3));
}

// ---------------- init ----------------
__global__ void init_kernel(float* __restrict__ out) {
    int idx = blockIdx.x * blockDim.x + threadIdx.x;
    int stride = gridDim.x * blockDim.x;
    for (size_t i = idx; i < (size_t)NTOK * DDIM; i += stride) out[i] = 0.0f;
    for (int i = idx; i < MAXROWS; i += stride) g_row_token[i] = -1;
    if (idx < NE) {
        g_counts[idx] = 0; g_fill[idx] = 0;
        g_psum[idx] = 0.0f; g_lsum[idx] = 0.0f;
    }
}

// ---------------- router ----------------
__global__ void router_kernel(const float* __restrict__ x,
                              const float* __restrict__ gw) {
    int t = blockIdx.x;
    int tid = threadIdx.x;
    float acc[NE];
#pragma unroll
    for (int e = 0; e < NE; e++) acc[e] = 0.0f;
    const float* xr = x + (size_t)t * DDIM;
    for (int d = tid; d < DDIM; d += 128) {
        float xv = xr[d];
        const float* g = gw + d * NE;
#pragma unroll
        for (int e = 0; e < NE; e++) acc[e] += xv * g[e];
    }
    __shared__ float red[128][NE + 1];
#pragma unroll
    for (int e = 0; e < NE; e++) red[tid][e] = acc[e];
    __syncthreads();
    for (int off = 64; off > 0; off >>= 1) {
        if (tid < off) {
#pragma unroll
            for (int e = 0; e < NE; e++) red[tid][e] += red[tid + off][e];
        }
        __syncthreads();
    }
    if (tid == 0) {
        float lg[NE], p[NE];
        float m = -1e30f;
#pragma unroll
        for (int e = 0; e < NE; e++) { lg[e] = red[0][e]; m = fmaxf(m, lg[e]); }
        float s = 0.0f;
#pragma unroll
        for (int e = 0; e < NE; e++) { p[e] = expf(lg[e] - m); s += p[e]; }
        float inv = 1.0f / s;
#pragma unroll
        for (int e = 0; e < NE; e++) p[e] *= inv;
        int i1 = 0;
#pragma unroll
        for (int e = 1; e < NE; e++) if (p[e] > p[i1]) i1 = e;
        int i2 = (i1 == 0) ? 1 : 0;
#pragma unroll
        for (int e = 0; e < NE; e++) if (e != i1 && p[e] > p[i2]) i2 = e;
        float wsum = p[i1] + p[i2];
        g_topk_i[t * 2 + 0] = i1;
        g_topk_i[t * 2 + 1] = i2;
        g_topk_w[t * 2 + 0] = p[i1] / wsum;
        g_topk_w[t * 2 + 1] = p[i2] / wsum;
        atomicAdd(&g_counts[i1], 1);
        atomicAdd(&g_counts[i2], 1);
#pragma unroll
        for (int e = 0; e < NE; e++) {
            atomicAdd(&g_psum[e], p[e]);
            atomicAdd(&g_lsum[e], lg[e]);
        }
    }
}

// ---------------- schedule ----------------
__global__ void schedule_kernel(float* __restrict__ out, long long out_size) {
    if (threadIdx.x != 0 || blockIdx.x != 0) return;
    int tile = 0;
    for (int slot = 0; slot < NSLOT; slot++) {
        int cnt = (slot < NE) ? g_counts[slot] : NTOK;
        g_offsets[slot] = tile * TM;
        int nt = (cnt + TM - 1) / TM;
        for (int i = 0; i < nt; i++) g_tile_slot[tile++] = slot;
    }
    for (; tile < MAXTILESM; tile++) g_tile_slot[tile] = -1;
    float aux = 0.0f;
    for (int e = 0; e < NE; e++)
        aux += (g_psum[e] * (1.0f / NTOK)) * (g_lsum[e] * (1.0f / NTOK));
    aux *= (float)NE;
    if (out_size > (long long)NTOK * DDIM) out[(size_t)NTOK * DDIM] = aux;
}

// ---------------- scatter ----------------
__global__ void scatter_kernel() {
    int i = blockIdx.x * blockDim.x + threadIdx.x;
    const int total = NTOK * TOPK + NTOK * NS;
    if (i >= total) return;
    if (i < NTOK * TOPK) {
        int e = g_topk_i[i];
        int pos = atomicAdd(&g_fill[e], 1);
        int row = g_offsets[e] + pos;
        g_row_token[row] = i >> 1;
        g_row_w[row] = g_topk_w[i];
    } else {
        int j = i - NTOK * TOPK;
        int s = j / NTOK, t = j % NTOK;
        int row = g_offsets[NE + s] + t;
        g_row_token[row] = t;
        g_row_w[row] = 1.0f;
    }
}

// ===== heterogeneous grouped FFN GEMM: mma CTAs + fp32 SIMT CTAs ============
// PHASE1: hidden = silu(gather(x) @ W1)   K=DDIM, N=HDIM -> g_hid (tiled hi/lo)
// PHASE2: out   += w_row * (hidden @ W2)  K=HDIM, N=DDIM (atomicAdd)
// bn < FP_SPLIT: tensor-core path (bf16 3-pass).  bn >= FP_SPLIT: fp32 FFMA path.
template <bool PHASE1>
__global__ __launch_bounds__(256, 2)
void ffn_mma(const float* __restrict__ x,
             const float* __restrict__ sw1, const float* __restrict__ sw2,
             const float* __restrict__ ew1, const float* __restrict__ ew2,
             float* __restrict__ out) {
    extern __shared__ char smem[];
    const int bn = blockIdx.x, bm = blockIdx.y;
    const int slot = g_tile_slot[bm];
    if (slot < 0) return;
    const int row0 = bm * TM, n0 = bn * TN;
    const int tid = threadIdx.x, wid = tid >> 5, lane = tid & 31;
    int* s_tok = (int*)(smem + OFF_TOK);
    float* s_w = (float*)(smem + OFF_W);
    if (tid < TM) {
        s_tok[tid] = g_row_token[row0 + tid];
        s_w[tid]   = g_row_w[row0 + tid];
    }
    __syncthreads();

    const int FPS = PHASE1 ? FP1_SPLIT : FP2_SPLIT;

    if (bn >= FPS) {
        // ================== fp32 SIMT path (CUDA cores) ==================
        const int KD = PHASE1 ? DDIM : HDIM;
        const int ND = PHASE1 ? HDIM : DDIM;
        const float* B;
        if (PHASE1)
            B = (slot < NE) ? ew1 + (size_t)slot * DDIM * HDIM
                            : sw1 + (size_t)(slot - NE) * DDIM * HDIM;
        else
            B = (slot < NE) ? ew2 + (size_t)slot * HDIM * DDIM
                            : sw2 + (size_t)(slot - NE) * HDIM * DDIM;
        float (*As)[TM + 4] = (float(*)[TM + 4])(smem + OFF_TILES);
        float (*Bs)[TN + 4] = (float(*)[TN + 4])(smem + OFF_TILES + TKF * (TM + 4) * 4);

        float acc[8][8];
#pragma unroll
        for (int i = 0; i < 8; i++)
#pragma unroll
            for (int j = 0; j < 8; j++) acc[i][j] = 0.0f;
        int tx = tid & 15, ty = tid >> 4;

        for (int k0 = 0; k0 < KD; k0 += TKF) {
#pragma unroll
            for (int i = 0; i < 2; i++) {
                int lid = tid + i * 256;
                int m = lid >> 2;
                int kk = (lid & 3) << 2;
                float a0, a1, a2, a3;
                if (PHASE1) {
                    int tok = s_tok[m];
                    if (tok >= 0) {
                        float4 v = *(const float4*)&x[(size_t)tok * DDIM + k0 + kk];
                        a0 = v.x; a1 = v.y; a2 = v.z; a3 = v.w;
                    } else { a0 = a1 = a2 = a3 = 0.0f; }
                } else {
                    int k = k0 + kk;
                    const __nv_bfloat16* hb = g_hid
                        + ((size_t)bm * NCH2 + (k >> 5)) * CHUNK_ELEM
                        + (size_t)m * KC + (k & 31);
                    uint2 hv = *(const uint2*)hb;
                    uint2 lv = *(const uint2*)(hb + 128 * KC);
                    float h0, h1, h2, h3, l0, l1, l2, l3;
                    unpk2(hv.x, h0, h1); unpk2(hv.y, h2, h3);
                    unpk2(lv.x, l0, l1); unpk2(lv.y, l2, l3);
                    a0 = h0 + l0; a1 = h1 + l1; a2 = h2 + l2; a3 = h3 + l3;
                }
                As[kk + 0][m] = a0; As[kk + 1][m] = a1;
                As[kk + 2][m] = a2; As[kk + 3][m] = a3;
            }
#pragma unroll
            for (int i = 0; i < 2; i++) {
                int lid = tid + i * 256;
                int k = lid >> 5;
                int nn = (lid & 31) << 2;
                *(float4*)&Bs[k][nn] =
                    *(const float4*)&B[(size_t)(k0 + k) * ND + n0 + nn];
            }
            __syncthreads();
#pragma unroll
            for (int k = 0; k < TKF; k++) {
                float a[8], b[8];
                *(float4*)&a[0] = *(const float4*)&As[k][ty * 8];
                *(float4*)&a[4] = *(const float4*)&As[k][ty * 8 + 4];
                *(float4*)&b[0] = *(const float4*)&Bs[k][tx * 8];
                *(float4*)&b[4] = *(const float4*)&Bs[k][tx * 8 + 4];
#pragma unroll
                for (int im = 0; im < 8; im++)
#pragma unroll
                    for (int in = 0; in < 8; in++)
                        acc[im][in] += a[im] * b[in];
            }
            __syncthreads();
        }

        if (PHASE1) {
#pragma unroll
            for (int im = 0; im < 8; im++) {
                int r = ty * 8 + im;
                int gcol = n0 + tx * 8;
                size_t base = ((size_t)bm * NCH2 + (gcol >> 5)) * CHUNK_ELEM
                              + (size_t)r * KC + (gcol & 31);
#pragma unroll
                for (int j = 0; j < 8; j += 2) {
                    float v0 = acc[im][j], v1 = acc[im][j + 1];
                    v0 = v0 / (1.0f + __expf(-v0));
                    v1 = v1 / (1.0f + __expf(-v1));
                    __nv_bfloat16 h0, h1, l0, l1;
                    split_bf(v0, h0, l0); split_bf(v1, h1, l1);
                    *(uint32_t*)(g_hid + base + j)            = pk(h0, h1);
                    *(uint32_t*)(g_hid + base + 128 * KC + j) = pk(l0, l1);
                }
            }
        } else {
#pragma unroll
            for (int im = 0; im < 8; im++) {
                int m = ty * 8 + im;
                int tok = s_tok[m];
                if (tok < 0) continue;
                float w = s_w[m];
                float* op = &out[(size_t)tok * DDIM + n0 + tx * 8];
#pragma unroll
                for (int in = 0; in < 8; in++)
                    atomicAdd(&op[in], w * acc[im][in]);
            }
        }
        return;
    }

    // ================== tensor-core path (bf16 3-pass) ==================
    const int NC = PHASE1 ? NCH1 : NCH2;

    int tDst[4], tLo[4];
#pragma unroll
    for (int i = 0; i < 4; i++) {
        int u = tid + i * 256;
        int rem = u & 511;
        tDst[i] = (rem >> 2) * PITCH + (rem & 3) * 16;
        tLo[i]  = u >> 9;
    }

    const uint4* srcB;
    if (PHASE1)
        srcB = (const uint4*)g_w1t + (size_t)(slot * NBN1 + bn) * NCH1 * 1024;
    else
        srcB = (const uint4*)g_w2t + (size_t)(slot * NBN2 + bn) * NCH2 * 1024;
    const uint4* srcA2 = 0;
    const char*  srcA1 = 0;
    int sub = tid & 1;
    if (PHASE1) {
        int lm = tid >> 1;
        int tok = s_tok[lm]; if (tok < 0) tok = 0;
        srcA1 = (const char*)(g_xc + (size_t)tok * NCH1 * 64);
    } else {
        srcA2 = (const uint4*)g_hid + (size_t)bm * NCH2 * 1024;
    }
    const int dA1 = (tid >> 1) * PITCH + sub * 32;

    const uint32_t sb = smem_u32(smem);
    const int warp_m = (wid >> 2) * 64;
    const int warp_n = (wid & 3) * 32;
    const int a_row = warp_m + (lane & 15);
    const int a_c8  = (lane >> 4) << 3;
    const int b_row = warp_n + (lane & 7) + ((lane >> 4) << 3);
    const int b_c8  = lane & 8;

    float acc[4][4][4];
#pragma unroll
    for (int i = 0; i < 4; i++)
#pragma unroll
        for (int j = 0; j < 4; j++)
#pragma unroll
            for (int k = 0; k < 4; k++) acc[i][j][k] = 0.0f;

    {
        if (PHASE1) {
            const uint4* p = (const uint4*)srcA1;
            *(uint4*)(smem + AHOF(0) + dA1)      = p[sub * 2];
            *(uint4*)(smem + AHOF(0) + dA1 + 16) = p[sub * 2 + 1];
            *(uint4*)(smem + ALOF(0) + dA1)      = p[4 + sub * 2];
            *(uint4*)(smem + ALOF(0) + dA1 + 16) = p[4 + sub * 2 + 1];
        } else {
#pragma unroll
            for (int i = 0; i < 4; i++)
                *(uint4*)(smem + (tLo[i] ? ALOF(0) : AHOF(0)) + tDst[i]) = srcA2[tid + i * 256];
        }
#pragma unroll
        for (int i = 0; i < 4; i++)
            *(uint4*)(smem + (tLo[i] ? BLOF(0) : BHOF(0)) + tDst[i]) = srcB[tid + i * 256];
    }
    __syncthreads();

    for (int c = 0; c < NC; c++) {
        const int buf = c & 1;
        const bool have = (c + 1 < NC);

        uint4 sA[4], sB[4];
        if (have) {
            if (PHASE1) {
                const uint4* p = (const uint4*)(srcA1 + (c + 1) * 128);
                sA[0] = p[sub * 2];     sA[1] = p[sub * 2 + 1];
                sA[2] = p[4 + sub * 2]; sA[3] = p[4 + sub * 2 + 1];
            } else {
                const uint4* p = srcA2 + (size_t)(c + 1) * 1024;
#pragma unroll
                for (int i = 0; i < 4; i++) sA[i] = p[tid + i * 256];
            }
            const uint4* q = srcB + (size_t)(c + 1) * 1024;
#pragma unroll
            for (int i = 0; i < 4; i++) sB[i] = q[tid + i * 256];
        }

        {
            const uint32_t ahb = sb + AHOF(buf), alb = sb + ALOF(buf);
            const uint32_t bhb = sb + BHOF(buf), blb = sb + BLOF(buf);
#pragma unroll
            for (int ks = 0; ks < 2; ks++) {
                const int kk = ks * 16;
                const uint32_t baddr = (uint32_t)(b_row * PITCH + (kk + b_c8) * 2);
                const uint32_t aaddr = (uint32_t)(a_row * PITCH + (kk + a_c8) * 2);
                uint32_t bh0[4], bh1[4], bl0[4], bl1[4];
                ldsm4(bh0, bhb + baddr);
                ldsm4(bh1, bhb + baddr + 16 * PITCH);
                ldsm4(bl0, blb + baddr);
                ldsm4(bl1, blb + baddr + 16 * PITCH);
#pragma unroll
                for (int mi = 0; mi < 4; mi++) {
                    uint32_t af[4];
                    ldsm4(af, ahb + aaddr + mi * 16 * PITCH);
                    mma16816(acc[mi][0], af, bh0); mma16816(acc[mi][1], af, bh0 + 2);
                    mma16816(acc[mi][2], af, bh1); mma16816(acc[mi][3], af, bh1 + 2);
                    mma16816(acc[mi][0], af, bl0); mma16816(acc[mi][1], af, bl0 + 2);
                    mma16816(acc[mi][2], af, bl1); mma16816(acc[mi][3], af, bl1 + 2);
                    ldsm4(af, alb + aaddr + mi * 16 * PITCH);
                    mma16816(acc[mi][0], af, bh0); mma16816(acc[mi][1], af, bh0 + 2);
                    mma16816(acc[mi][2], af, bh1); mma16816(acc[mi][3], af, bh1 + 2);
                }
            }
        }

        if (have) {
            const int nb = (c + 1) & 1;
            if (PHASE1) {
                *(uint4*)(smem + AHOF(nb) + dA1)      = sA[0];
                *(uint4*)(smem + AHOF(nb) + dA1 + 16) = sA[1];
                *(uint4*)(smem + ALOF(nb) + dA1)      = sA[2];
                *(uint4*)(smem + ALOF(nb) + dA1 + 16) = sA[3];
            } else {
#pragma unroll
                for (int i = 0; i < 4; i++)
                    *(uint4*)(smem + (tLo[i] ? ALOF(nb) : AHOF(nb)) + tDst[i]) = sA[i];
            }
#pragma unroll
            for (int i = 0; i < 4; i++)
                *(uint4*)(smem + (tLo[i] ? BLOF(nb) : BHOF(nb)) + tDst[i]) = sB[i];
        }
        __syncthreads();
    }

    // -------- epilogue (mma path) --------
    const int gid = lane >> 2, tig = lane & 3;
#pragma unroll
    for (int mi = 0; mi < 4; mi++) {
#pragma unroll
        for (int f = 0; f < 4; f++) {
            const int col = n0 + warp_n + f * 8 + tig * 2;
#pragma unroll
            for (int h = 0; h < 2; h++) {
                const int r = warp_m + mi * 16 + gid + h * 8;
                float v0 = acc[mi][f][2 * h];
                float v1 = acc[mi][f][2 * h + 1];
                if (PHASE1) {
                    v0 = v0 / (1.0f + __expf(-v0));
                    v1 = v1 / (1.0f + __expf(-v1));
                    __nv_bfloat16 h0, h1, l0, l1;
                    split_bf(v0, h0, l0); split_bf(v1, h1, l1);
                    size_t base = ((size_t)bm * NCH2 + (col >> 5)) * CHUNK_ELEM
                                  + (size_t)r * KC + (col & 31);
                    *(uint32_t*)(g_hid + base)            = pk(h0, h1);
                    *(uint32_t*)(g_hid + base + 128 * KC) = pk(l0, l1);
                } else {
                    int tok = s_tok[r];
                    if (tok >= 0) {
                        float w = s_w[r];
                        float* op = out + (size_t)tok * DDIM + col;
                        atomicAdd(op,     w * v0);
                        atomicAdd(op + 1, w * v1);
                    }
                }
            }
        }
    }
}

// ---------------- launch ----------------
extern "C" void kernel_launch(void* const* d_in, const int* in_sizes, int n_in,
                              void* d_out, int out_size) {
    const float* x   = (const float*)d_in[0];
    const float* gw  = (const float*)d_in[1];
    const float* sw1 = (const float*)d_in[2];
    const float* sw2 = (const float*)d_in[3];
    const float* ew1 = (const float*)d_in[4];
    const float* ew2 = (const float*)d_in[5];
    float* out = (float*)d_out;

    cudaFuncSetAttribute(ffn_mma<true>,  cudaFuncAttributeMaxDynamicSharedMemorySize, SMEM_BYTES);
    cudaFuncSetAttribute(ffn_mma<false>, cudaFuncAttributeMaxDynamicSharedMemorySize, SMEM_BYTES);

    init_kernel<<<1024, 256>>>(out);
    router_kernel<<<NTOK, 128>>>(x, gw);
    schedule_kernel<<<1, 32>>>(out, (long long)out_size);
    scatter_kernel<<<(NTOK * (TOPK + NS) + 255) / 256, 256>>>();

    dim3 tb(32, 8);
    conv_w<1><<<dim3(DDIM / 32, HDIM / 32, NSLOT), tb>>>(ew1, sw1);
    conv_w<2><<<dim3(HDIM / 32, DDIM / 32, NSLOT), tb>>>(ew2, sw2);
    conv_x<<<(NTOK * DDIM / 4 + 255) / 256, 256>>>(x);

    // bn on fast axis -> each residency wave mixes mma and fp32 CTAs
    dim3 g1(NBN1, MAXTILESM);   // 11 x 144
    dim3 g2(NBN2, MAXTILESM);   // 16 x 144
    ffn_mma<true ><<<g1, 256, SMEM_BYTES>>>(x, sw1, sw2, ew1, ew2, out);
    ffn_mma<false><<<g2, 256, SMEM_BYTES>>>(x, sw1, sw2, ew1, ew2, out);
}

// round 10
// speedup vs baseline: 3.2862x; 2.1237x over previous
#include <cuda_runtime.h>
#include <cuda_fp16.h>
#include <cstdint>
#include <math.h>

// ---------------- problem constants ----------------
#define NTOK 4096
#define DDIM 2048
#define HDIM 1408
#define NE   16
#define NS   2
#define NSLOT (NE + NS)
#define TOPK 2
#define TM 128
#define TN 128
#define KC 32
#define MAXROWS (NTOK*TOPK + NE*TM + NTOK*NS)   // 18432
#define MAXTILESM (MAXROWS / TM)                // 144
#define NBN1 (HDIM / TN)     // 11
#define NCH1 (DDIM / KC)     // 64
#define NBN2 (DDIM / TN)     // 16
#define NCH2 (HDIM / KC)     // 44
#define WCH  4096            // weight chunk elems: 128n x 32k fp16
#define ACH  8192            // hidden chunk elems: hi 128x32 + lo 128x32

// smem tile geometry: rows of 32 fp16 + 16 pad = 80 bytes
#define PITCH 80
#define TILEB (128 * PITCH)          // 10240 B
#define OFF_TOK 0
#define OFF_W   512
#define OFF_TILES 1024
#define AHOF(b) (OFF_TILES + (b)*3*TILEB)
#define ALOF(b) (AHOF(b) + TILEB)
#define BHOF(b) (AHOF(b) + 2*TILEB)
#define SMEM_BYTES (OFF_TILES + 6*TILEB)   // 62464

// ---------------- device scratch (tiled layouts) ----------------
__device__ __align__(16) __half g_w1t[(size_t)NSLOT * NBN1 * NCH1 * WCH];
__device__ __align__(16) __half g_w2t[(size_t)NSLOT * NBN2 * NCH2 * WCH];
__device__ __align__(16) __half g_xc[(size_t)NTOK * NCH1 * 64];     // [tok][c][hi32|lo32]
__device__ __align__(16) __half g_hid[(size_t)MAXTILESM * NCH2 * ACH];
__device__ int   g_row_token[MAXROWS];
__device__ float g_row_w[MAXROWS];
__device__ int   g_tile_slot[MAXTILESM];
__device__ int   g_topk_i[NTOK * TOPK];
__device__ float g_topk_w[NTOK * TOPK];
__device__ int   g_counts[NE];
__device__ int   g_fill[NE];
__device__ int   g_offsets[NSLOT];
__device__ float g_psum[NE];
__device__ float g_lsum[NE];

// ---------------- helpers ----------------
__device__ __forceinline__ uint32_t smem_u32(const void* p) {
    uint32_t a;
    asm("{ .reg .u64 t; cvta.to.shared.u64 t, %1; cvt.u32.u64 %0, t; }"
        : "=r"(a) : "l"(p));
    return a;
}
__device__ __forceinline__ void ldsm4(uint32_t* r, uint32_t addr) {
    asm volatile("ldmatrix.sync.aligned.m8n8.x4.shared.b16 {%0,%1,%2,%3}, [%4];"
                 : "=r"(r[0]), "=r"(r[1]), "=r"(r[2]), "=r"(r[3]) : "r"(addr));
}
__device__ __forceinline__ void mmaf16(float* d, const uint32_t* a, const uint32_t* b) {
    asm volatile("mma.sync.aligned.m16n8k16.row.col.f32.f16.f16.f32 "
                 "{%0,%1,%2,%3}, {%4,%5,%6,%7}, {%8,%9}, {%0,%1,%2,%3};"
                 : "+f"(d[0]), "+f"(d[1]), "+f"(d[2]), "+f"(d[3])
                 : "r"(a[0]), "r"(a[1]), "r"(a[2]), "r"(a[3]), "r"(b[0]), "r"(b[1]));
}
__device__ __forceinline__ uint32_t pkh(__half a, __half b) {
    return (uint32_t)__half_as_ushort(a) | ((uint32_t)__half_as_ushort(b) << 16);
}
__device__ __forceinline__ void split_h(float v, __half& h, __half& l) {
    h = __float2half_rn(v);
    l = __float2half_rn(v - __half2float(h));
}

// ------- weight transpose + single fp16 round into tiled layout -------------
// dst chunk: [slot][bn][c][n(128)][k(32)] fp16
template <int PH>
__global__ void conv_w(const float* __restrict__ ew, const float* __restrict__ sw) {
    const int K = (PH == 1) ? DDIM : HDIM;
    const int N = (PH == 1) ? HDIM : DDIM;
    const int NBN = (PH == 1) ? NBN1 : NBN2;
    const int NCH = (PH == 1) ? NCH1 : NCH2;
    __half* dst = (PH == 1) ? g_w1t : g_w2t;
    int slot = blockIdx.z;
    const float* src = (slot < NE) ? ew + (size_t)slot * K * N
                                   : sw + (size_t)(slot - NE) * K * N;
    __shared__ float t[32][33];
    int k0 = blockIdx.x * 32, n0 = blockIdx.y * 32;
    int tx = threadIdx.x, ty = threadIdx.y;   // 32, 8
#pragma unroll
    for (int i = 0; i < 4; i++)
        t[ty + i * 8][tx] = src[(size_t)(k0 + ty + i * 8) * N + n0 + tx];
    __syncthreads();
    const int c = k0 >> 5;
#pragma unroll
    for (int i = 0; i < 4; i++) {
        int n = n0 + ty + i * 8;
        float v = t[tx][ty + i * 8];                 // src[k0+tx][n]
        size_t base = ((size_t)(slot * NBN + (n >> 7)) * NCH + c) * WCH
                      + (size_t)(n & 127) * 32 + tx;
        dst[base] = __float2half_rn(v);
    }
}

// ---------------- x split (fp16 hi/lo) into chunk-interleaved layout --------
__global__ void conv_x(const float* __restrict__ x) {
    size_t i = ((size_t)blockIdx.x * blockDim.x + threadIdx.x) * 4;
    if (i >= (size_t)NTOK * DDIM) return;
    float4 v = *(const float4*)(x + i);
    __half h0, h1, h2, h3, l0, l1, l2, l3;
    split_h(v.x, h0, l0); split_h(v.y, h1, l1);
    split_h(v.z, h2, l2); split_h(v.w, h3, l3);
    int tok = (int)(i >> 11);
    int k = (int)(i & 2047);
    size_t base = ((size_t)tok * NCH1 + (k >> 5)) * 64 + (k & 31);
    *(uint2*)(g_xc + base)      = make_uint2(pkh(h0, h1), pkh(h2, h3));
    *(uint2*)(g_xc + base + 32) = make_uint2(pkh(l0, l1), pkh(l2, l3));
}

// ---------------- init ----------------
__global__ void init_kernel(float* __restrict__ out) {
    int idx = blockIdx.x * blockDim.x + threadIdx.x;
    int stride = gridDim.x * blockDim.x;
    for (size_t i = idx; i < (size_t)NTOK * DDIM; i += stride) out[i] = 0.0f;
    for (int i = idx; i < MAXROWS; i += stride) g_row_token[i] = -1;
    if (idx < NE) {
        g_counts[idx] = 0; g_fill[idx] = 0;
        g_psum[idx] = 0.0f; g_lsum[idx] = 0.0f;
    }
}

// ---------------- router ----------------
__global__ void router_kernel(const float* __restrict__ x,
                              const float* __restrict__ gw) {
    int t = blockIdx.x;
    int tid = threadIdx.x;
    float acc[NE];
#pragma unroll
    for (int e = 0; e < NE; e++) acc[e] = 0.0f;
    const float* xr = x + (size_t)t * DDIM;
    for (int d = tid; d < DDIM; d += 128) {
        float xv = xr[d];
        const float* g = gw + d * NE;
#pragma unroll
        for (int e = 0; e < NE; e++) acc[e] += xv * g[e];
    }
    __shared__ float red[128][NE + 1];
#pragma unroll
    for (int e = 0; e < NE; e++) red[tid][e] = acc[e];
    __syncthreads();
    for (int off = 64; off > 0; off >>= 1) {
        if (tid < off) {
#pragma unroll
            for (int e = 0; e < NE; e++) red[tid][e] += red[tid + off][e];
        }
        __syncthreads();
    }
    if (tid == 0) {
        float lg[NE], p[NE];
        float m = -1e30f;
#pragma unroll
        for (int e = 0; e < NE; e++) { lg[e] = red[0][e]; m = fmaxf(m, lg[e]); }
        float s = 0.0f;
#pragma unroll
        for (int e = 0; e < NE; e++) { p[e] = expf(lg[e] - m); s += p[e]; }
        float inv = 1.0f / s;
#pragma unroll
        for (int e = 0; e < NE; e++) p[e] *= inv;
        int i1 = 0;
#pragma unroll
        for (int e = 1; e < NE; e++) if (p[e] > p[i1]) i1 = e;
        int i2 = (i1 == 0) ? 1 : 0;
#pragma unroll
        for (int e = 0; e < NE; e++) if (e != i1 && p[e] > p[i2]) i2 = e;
        float wsum = p[i1] + p[i2];
        g_topk_i[t * 2 + 0] = i1;
        g_topk_i[t * 2 + 1] = i2;
        g_topk_w[t * 2 + 0] = p[i1] / wsum;
        g_topk_w[t * 2 + 1] = p[i2] / wsum;
        atomicAdd(&g_counts[i1], 1);
        atomicAdd(&g_counts[i2], 1);
#pragma unroll
        for (int e = 0; e < NE; e++) {
            atomicAdd(&g_psum[e], p[e]);
            atomicAdd(&g_lsum[e], lg[e]);
        }
    }
}

// ---------------- schedule ----------------
__global__ void schedule_kernel(float* __restrict__ out, long long out_size) {
    if (threadIdx.x != 0 || blockIdx.x != 0) return;
    int tile = 0;
    for (int slot = 0; slot < NSLOT; slot++) {
        int cnt = (slot < NE) ? g_counts[slot] : NTOK;
        g_offsets[slot] = tile * TM;
        int nt = (cnt + TM - 1) / TM;
        for (int i = 0; i < nt; i++) g_tile_slot[tile++] = slot;
    }
    for (; tile < MAXTILESM; tile++) g_tile_slot[tile] = -1;
    float aux = 0.0f;
    for (int e = 0; e < NE; e++)
        aux += (g_psum[e] * (1.0f / NTOK)) * (g_lsum[e] * (1.0f / NTOK));
    aux *= (float)NE;
    if (out_size > (long long)NTOK * DDIM) out[(size_t)NTOK * DDIM] = aux;
}

// ---------------- scatter ----------------
__global__ void scatter_kernel() {
    int i = blockIdx.x * blockDim.x + threadIdx.x;
    const int total = NTOK * TOPK + NTOK * NS;
    if (i >= total) return;
    if (i < NTOK * TOPK) {
        int e = g_topk_i[i];
        int pos = atomicAdd(&g_fill[e], 1);
        int row = g_offsets[e] + pos;
        g_row_token[row] = i >> 1;
        g_row_w[row] = g_topk_w[i];
    } else {
        int j = i - NTOK * TOPK;
        int s = j / NTOK, t = j % NTOK;
        int row = g_offsets[NE + s] + t;
        g_row_token[row] = t;
        g_row_w[row] = 1.0f;
    }
}

// ----- fp16 2-pass grouped FFN GEMM: acc = (Ah+Al)·Bh, B single-rounded -----
// PHASE1: hidden = silu(gather(x) @ W1)   K=DDIM -> g_hid (tiled fp16 hi/lo)
// PHASE2: out   += w_row * (hidden @ W2)  K=HDIM (atomicAdd)
template <bool PHASE1>
__global__ __launch_bounds__(256, 2)
void ffn_mma(float* __restrict__ out) {
    extern __shared__ char smem[];
    const int bm = blockIdx.x, bn = blockIdx.y;
    const int slot = g_tile_slot[bm];
    if (slot < 0) return;
    const int NC = PHASE1 ? NCH1 : NCH2;
    const int row0 = bm * TM, n0 = bn * TN;
    const int tid = threadIdx.x, wid = tid >> 5, lane = tid & 31;
    int* s_tok = (int*)(smem + OFF_TOK);
    float* s_w = (float*)(smem + OFF_W);
    if (tid < TM) {
        s_tok[tid] = g_row_token[row0 + tid];
        s_w[tid]   = g_row_w[row0 + tid];
    }
    __syncthreads();

    // ---- loader offsets ----
    // B: 512 u4/chunk, 2 per thread.  A(phase2): 1024 u4/chunk (hi|lo), 4 per thread.
    int bDst[2];
#pragma unroll
    for (int i = 0; i < 2; i++) {
        int u = tid + i * 256;
        bDst[i] = (u >> 2) * PITCH + (u & 3) * 16;
    }
    int aDst[4], aLo[4];
#pragma unroll
    for (int i = 0; i < 4; i++) {
        int u = tid + i * 256;
        int rem = u & 511;
        aDst[i] = (rem >> 2) * PITCH + (rem & 3) * 16;
        aLo[i]  = u >> 9;
    }

    const uint4* srcB = PHASE1
        ? (const uint4*)g_w1t + (size_t)(slot * NBN1 + bn) * NCH1 * 512
        : (const uint4*)g_w2t + (size_t)(slot * NBN2 + bn) * NCH2 * 512;
    const uint4* srcA2 = 0;
    const uint4* srcA1 = 0;
    const int sub = tid & 1;                 // phase1: 0=hi half, 1=lo half
    if (PHASE1) {
        int tok = s_tok[tid >> 1]; if (tok < 0) tok = 0;
        srcA1 = (const uint4*)(g_xc + (size_t)tok * NCH1 * 64) + sub * 4;
    } else {
        srcA2 = (const uint4*)g_hid + (size_t)bm * NCH2 * 1024;
    }
    const int dA1 = (tid >> 1) * PITCH;      // 4 consecutive u4 per thread

    const uint32_t sb = smem_u32(smem);
    const int warp_m = (wid >> 2) * 64;
    const int warp_n = (wid & 3) * 32;
    const int a_row = warp_m + (lane & 15);
    const int a_c8  = (lane >> 4) << 3;
    const int b_row = warp_n + (lane & 7) + ((lane >> 4) << 3);
    const int b_c8  = lane & 8;

    float acc[4][4][4];
#pragma unroll
    for (int i = 0; i < 4; i++)
#pragma unroll
        for (int j = 0; j < 4; j++)
#pragma unroll
            for (int k = 0; k < 4; k++) acc[i][j][k] = 0.0f;

    // -------- direct load of chunk 0 --------
    {
        if (PHASE1) {
            char* base = smem + (sub ? ALOF(0) : AHOF(0)) + dA1;
#pragma unroll
            for (int i = 0; i < 4; i++)
                *(uint4*)(base + i * 16) = srcA1[i];
        } else {
#pragma unroll
            for (int i = 0; i < 4; i++)
                *(uint4*)(smem + (aLo[i] ? ALOF(0) : AHOF(0)) + aDst[i]) = srcA2[tid + i * 256];
        }
#pragma unroll
        for (int i = 0; i < 2; i++)
            *(uint4*)(smem + BHOF(0) + bDst[i]) = srcB[tid + i * 256];
    }
    __syncthreads();

    // -------- main loop --------
    for (int c = 0; c < NC; c++) {
        const int buf = c & 1;
        const bool have = (c + 1 < NC);

        uint4 sA[4], sB[2];
        if (have) {
            if (PHASE1) {
                const uint4* p = srcA1 + (size_t)(c + 1) * 8;
#pragma unroll
                for (int i = 0; i < 4; i++) sA[i] = p[i];
            } else {
                const uint4* p = srcA2 + (size_t)(c + 1) * 1024;
#pragma unroll
                for (int i = 0; i < 4; i++) sA[i] = p[tid + i * 256];
            }
            const uint4* q = srcB + (size_t)(c + 1) * 512;
            sB[0] = q[tid]; sB[1] = q[tid + 256];
        }

        // ---- compute on buffer `buf` ----
        {
            const uint32_t ahb = sb + AHOF(buf), alb = sb + ALOF(buf);
            const uint32_t bhb = sb + BHOF(buf);
#pragma unroll
            for (int ks = 0; ks < 2; ks++) {
                const int kk = ks * 16;
                const uint32_t baddr = (uint32_t)(b_row * PITCH + (kk + b_c8) * 2);
                const uint32_t aaddr = (uint32_t)(a_row * PITCH + (kk + a_c8) * 2);
                uint32_t bh0[4], bh1[4];
                ldsm4(bh0, bhb + baddr);
                ldsm4(bh1, bhb + baddr + 16 * PITCH);
#pragma unroll
                for (int mi = 0; mi < 4; mi++) {
                    uint32_t af[4];
                    ldsm4(af, ahb + aaddr + mi * 16 * PITCH);
                    mmaf16(acc[mi][0], af, bh0); mmaf16(acc[mi][1], af, bh0 + 2);
                    mmaf16(acc[mi][2], af, bh1); mmaf16(acc[mi][3], af, bh1 + 2);
                    ldsm4(af, alb + aaddr + mi * 16 * PITCH);
                    mmaf16(acc[mi][0], af, bh0); mmaf16(acc[mi][1], af, bh0 + 2);
                    mmaf16(acc[mi][2], af, bh1); mmaf16(acc[mi][3], af, bh1 + 2);
                }
            }
        }

        // ---- STS staged chunk into other buffer ----
        if (have) {
            const int nb = (c + 1) & 1;
            if (PHASE1) {
                char* base = smem + (sub ? ALOF(nb) : AHOF(nb)) + dA1;
#pragma unroll
                for (int i = 0; i < 4; i++)
                    *(uint4*)(base + i * 16) = sA[i];
            } else {
#pragma unroll
                for (int i = 0; i < 4; i++)
                    *(uint4*)(smem + (aLo[i] ? ALOF(nb) : AHOF(nb)) + aDst[i]) = sA[i];
            }
            *(uint4*)(smem + BHOF(nb) + bDst[0]) = sB[0];
            *(uint4*)(smem + BHOF(nb) + bDst[1]) = sB[1];
        }
        __syncthreads();
    }

    // -------- epilogue --------
    const int gid = lane >> 2, tig = lane & 3;
#pragma unroll
    for (int mi = 0; mi < 4; mi++) {
#pragma unroll
        for (int f = 0; f < 4; f++) {
            const int col = n0 + warp_n + f * 8 + tig * 2;
#pragma unroll
            for (int h = 0; h < 2; h++) {
                const int r = warp_m + mi * 16 + gid + h * 8;
                float v0 = acc[mi][f][2 * h];
                float v1 = acc[mi][f][2 * h + 1];
                if (PHASE1) {
                    v0 = v0 / (1.0f + __expf(-v0));
                    v1 = v1 / (1.0f + __expf(-v1));
                    __half h0, h1, l0, l1;
                    split_h(v0, h0, l0); split_h(v1, h1, l1);
                    // hidden tiled: [bm][col>>5][hi 128x32 | lo 128x32]
                    size_t base = ((size_t)bm * NCH2 + (col >> 5)) * ACH
                                  + (size_t)r * 32 + (col & 31);
                    *(uint32_t*)(g_hid + base)        = pkh(h0, h1);
                    *(uint32_t*)(g_hid + base + 4096) = pkh(l0, l1);
                } else {
                    int tok = s_tok[r];
                    if (tok >= 0) {
                        float w = s_w[r];
                        float* op = out + (size_t)tok * DDIM + col;
                        atomicAdd(op,     w * v0);
                        atomicAdd(op + 1, w * v1);
                    }
                }
            }
        }
    }
}

// ---------------- launch ----------------
extern "C" void kernel_launch(void* const* d_in, const int* in_sizes, int n_in,
                              void* d_out, int out_size) {
    const float* x   = (const float*)d_in[0];
    const float* gw  = (const float*)d_in[1];
    const float* sw1 = (const float*)d_in[2];
    const float* sw2 = (const float*)d_in[3];
    const float* ew1 = (const float*)d_in[4];
    const float* ew2 = (const float*)d_in[5];
    float* out = (float*)d_out;

    cudaFuncSetAttribute(ffn_mma<true>,  cudaFuncAttributeMaxDynamicSharedMemorySize, SMEM_BYTES);
    cudaFuncSetAttribute(ffn_mma<false>, cudaFuncAttributeMaxDynamicSharedMemorySize, SMEM_BYTES);

    init_kernel<<<1024, 256>>>(out);
    router_kernel<<<NTOK, 128>>>(x, gw);
    schedule_kernel<<<1, 32>>>(out, (long long)out_size);
    scatter_kernel<<<(NTOK * (TOPK + NS) + 255) / 256, 256>>>();

    dim3 tb(32, 8);
    conv_w<1><<<dim3(DDIM / 32, HDIM / 32, NSLOT), tb>>>(ew1, sw1);
    conv_w<2><<<dim3(HDIM / 32, DDIM / 32, NSLOT), tb>>>(ew2, sw2);
    conv_x<<<(NTOK * DDIM / 4 + 255) / 256, 256>>>(x);

    dim3 g1(MAXTILESM, NBN1);   // 144 x 11
    dim3 g2(MAXTILESM, NBN2);   // 144 x 16
    ffn_mma<true ><<<g1, 256, SMEM_BYTES>>>(out);
    ffn_mma<false><<<g2, 256, SMEM_BYTES>>>(out);
}

// round 11
// speedup vs baseline: 4.7207x; 1.4365x over previous
#include <cuda_runtime.h>
#include <cuda_fp16.h>
#include <cstdint>
#include <math.h>

// ---------------- problem constants ----------------
#define NTOK 4096
#define DDIM 2048
#define HDIM 1408
#define NE   16
#define NS   2
#define NSLOT (NE + NS)
#define TOPK 2
#define TM 128
#define TN 128
#define KC 32
#define MAXROWS (NTOK*TOPK + NE*TM + NTOK*NS)   // 18432
#define MAXTILESM (MAXROWS / TM)                // 144
#define NBN1 (HDIM / TN)     // 11
#define NCH1 (DDIM / KC)     // 64
#define NBN2 (DDIM / TN)     // 16
#define NCH2 (HDIM / KC)     // 44
#define WCH  4096            // weight chunk elems: 128n x 32k fp16
#define ACH  4096            // hidden chunk elems: 128m x 32k fp16

// smem tile geometry: rows of 32 fp16 + 16 pad = 80 bytes
#define PITCH 80
#define TILEB (128 * PITCH)          // 10240 B
#define OFF_TOK 0
#define OFF_W   512
#define OFF_TILES 1024
#define AOF(b) (OFF_TILES + (b)*2*TILEB)
#define BOF(b) (AOF(b) + TILEB)
#define SMEM_BYTES (OFF_TILES + 4*TILEB)   // 41984

// ---------------- device scratch (tiled layouts) ----------------
__device__ __align__(16) __half g_w1t[(size_t)NSLOT * NBN1 * NCH1 * WCH];
__device__ __align__(16) __half g_w2t[(size_t)NSLOT * NBN2 * NCH2 * WCH];
__device__ __align__(16) __half g_xc[(size_t)NTOK * NCH1 * 32];     // [tok][c][32]
__device__ __align__(16) __half g_hid[(size_t)MAXTILESM * NCH2 * ACH];
__device__ int   g_row_token[MAXROWS];
__device__ float g_row_w[MAXROWS];
__device__ int   g_tile_slot[MAXTILESM];
__device__ int   g_topk_i[NTOK * TOPK];
__device__ float g_topk_w[NTOK * TOPK];
__device__ int   g_counts[NE];
__device__ int   g_fill[NE];
__device__ int   g_offsets[NSLOT];
__device__ float g_psum[NE];
__device__ float g_lsum[NE];

// ---------------- helpers ----------------
__device__ __forceinline__ uint32_t smem_u32(const void* p) {
    uint32_t a;
    asm("{ .reg .u64 t; cvta.to.shared.u64 t, %1; cvt.u32.u64 %0, t; }"
        : "=r"(a) : "l"(p));
    return a;
}
__device__ __forceinline__ void ldsm4(uint32_t* r, uint32_t addr) {
    asm volatile("ldmatrix.sync.aligned.m8n8.x4.shared.b16 {%0,%1,%2,%3}, [%4];"
                 : "=r"(r[0]), "=r"(r[1]), "=r"(r[2]), "=r"(r[3]) : "r"(addr));
}
__device__ __forceinline__ void mmaf16(float* d, const uint32_t* a, const uint32_t* b) {
    asm volatile("mma.sync.aligned.m16n8k16.row.col.f32.f16.f16.f32 "
                 "{%0,%1,%2,%3}, {%4,%5,%6,%7}, {%8,%9}, {%0,%1,%2,%3};"
                 : "+f"(d[0]), "+f"(d[1]), "+f"(d[2]), "+f"(d[3])
                 : "r"(a[0]), "r"(a[1]), "r"(a[2]), "r"(a[3]), "r"(b[0]), "r"(b[1]));
}
__device__ __forceinline__ uint32_t pkh(__half a, __half b) {
    return (uint32_t)__half_as_ushort(a) | ((uint32_t)__half_as_ushort(b) << 16);
}

// ------- weight transpose + fp16 round into tiled layout --------------------
template <int PH>
__global__ void conv_w(const float* __restrict__ ew, const float* __restrict__ sw) {
    const int K = (PH == 1) ? DDIM : HDIM;
    const int N = (PH == 1) ? HDIM : DDIM;
    const int NBN = (PH == 1) ? NBN1 : NBN2;
    const int NCH = (PH == 1) ? NCH1 : NCH2;
    __half* dst = (PH == 1) ? g_w1t : g_w2t;
    int slot = blockIdx.z;
    const float* src = (slot < NE) ? ew + (size_t)slot * K * N
                                   : sw + (size_t)(slot - NE) * K * N;
    __shared__ float t[32][33];
    int k0 = blockIdx.x * 32, n0 = blockIdx.y * 32;
    int tx = threadIdx.x, ty = threadIdx.y;   // 32, 8
#pragma unroll
    for (int i = 0; i < 4; i++)
        t[ty + i * 8][tx] = src[(size_t)(k0 + ty + i * 8) * N + n0 + tx];
    __syncthreads();
    const int c = k0 >> 5;
#pragma unroll
    for (int i = 0; i < 4; i++) {
        int n = n0 + ty + i * 8;
        float v = t[tx][ty + i * 8];                 // src[k0+tx][n]
        size_t base = ((size_t)(slot * NBN + (n >> 7)) * NCH + c) * WCH
                      + (size_t)(n & 127) * 32 + tx;
        dst[base] = __float2half_rn(v);
    }
}

// ---------------- x fp16 round into chunk-interleaved layout ----------------
__global__ void conv_x(const float* __restrict__ x) {
    size_t i = ((size_t)blockIdx.x * blockDim.x + threadIdx.x) * 4;
    if (i >= (size_t)NTOK * DDIM) return;
    float4 v = *(const float4*)(x + i);
    // layout matches linear order within token: [tok][c][k&31] with c=k>>5
    *(uint2*)(g_xc + i) = make_uint2(
        pkh(__float2half_rn(v.x), __float2half_rn(v.y)),
        pkh(__float2half_rn(v.z), __float2half_rn(v.w)));
}

// ---------------- init ----------------
__global__ void init_kernel(float* __restrict__ out) {
    int idx = blockIdx.x * blockDim.x + threadIdx.x;
    int stride = gridDim.x * blockDim.x;
    for (size_t i = idx; i < (size_t)NTOK * DDIM; i += stride) out[i] = 0.0f;
    for (int i = idx; i < MAXROWS; i += stride) g_row_token[i] = -1;
    if (idx < NE) {
        g_counts[idx] = 0; g_fill[idx] = 0;
        g_psum[idx] = 0.0f; g_lsum[idx] = 0.0f;
    }
}

// ---------------- router ----------------
__global__ void router_kernel(const float* __restrict__ x,
                              const float* __restrict__ gw) {
    int t = blockIdx.x;
    int tid = threadIdx.x;
    float acc[NE];
#pragma unroll
    for (int e = 0; e < NE; e++) acc[e] = 0.0f;
    const float* xr = x + (size_t)t * DDIM;
    for (int d = tid; d < DDIM; d += 128) {
        float xv = xr[d];
        const float* g = gw + d * NE;
#pragma unroll
        for (int e = 0; e < NE; e++) acc[e] += xv * g[e];
    }
    __shared__ float red[128][NE + 1];
#pragma unroll
    for (int e = 0; e < NE; e++) red[tid][e] = acc[e];
    __syncthreads();
    for (int off = 64; off > 0; off >>= 1) {
        if (tid < off) {
#pragma unroll
            for (int e = 0; e < NE; e++) red[tid][e] += red[tid + off][e];
        }
        __syncthreads();
    }
    if (tid == 0) {
        float lg[NE], p[NE];
        float m = -1e30f;
#pragma unroll
        for (int e = 0; e < NE; e++) { lg[e] = red[0][e]; m = fmaxf(m, lg[e]); }
        float s = 0.0f;
#pragma unroll
        for (int e = 0; e < NE; e++) { p[e] = expf(lg[e] - m); s += p[e]; }
        float inv = 1.0f / s;
#pragma unroll
        for (int e = 0; e < NE; e++) p[e] *= inv;
        int i1 = 0;
#pragma unroll
        for (int e = 1; e < NE; e++) if (p[e] > p[i1]) i1 = e;
        int i2 = (i1 == 0) ? 1 : 0;
#pragma unroll
        for (int e = 0; e < NE; e++) if (e != i1 && p[e] > p[i2]) i2 = e;
        float wsum = p[i1] + p[i2];
        g_topk_i[t * 2 + 0] = i1;
        g_topk_i[t * 2 + 1] = i2;
        g_topk_w[t * 2 + 0] = p[i1] / wsum;
        g_topk_w[t * 2 + 1] = p[i2] / wsum;
        atomicAdd(&g_counts[i1], 1);
        atomicAdd(&g_counts[i2], 1);
#pragma unroll
        for (int e = 0; e < NE; e++) {
            atomicAdd(&g_psum[e], p[e]);
            atomicAdd(&g_lsum[e], lg[e]);
        }
    }
}

// ---------------- schedule ----------------
__global__ void schedule_kernel(float* __restrict__ out, long long out_size) {
    if (threadIdx.x != 0 || blockIdx.x != 0) return;
    int tile = 0;
    for (int slot = 0; slot < NSLOT; slot++) {
        int cnt = (slot < NE) ? g_counts[slot] : NTOK;
        g_offsets[slot] = tile * TM;
        int nt = (cnt + TM - 1) / TM;
        for (int i = 0; i < nt; i++) g_tile_slot[tile++] = slot;
    }
    for (; tile < MAXTILESM; tile++) g_tile_slot[tile] = -1;
    float aux = 0.0f;
    for (int e = 0; e < NE; e++)
        aux += (g_psum[e] * (1.0f / NTOK)) * (g_lsum[e] * (1.0f / NTOK));
    aux *= (float)NE;
    if (out_size > (long long)NTOK * DDIM) out[(size_t)NTOK * DDIM] = aux;
}

// ---------------- scatter ----------------
__global__ void scatter_kernel() {
    int i = blockIdx.x * blockDim.x + threadIdx.x;
    const int total = NTOK * TOPK + NTOK * NS;
    if (i >= total) return;
    if (i < NTOK * TOPK) {
        int e = g_topk_i[i];
        int pos = atomicAdd(&g_fill[e], 1);
        int row = g_offsets[e] + pos;
        g_row_token[row] = i >> 1;
        g_row_w[row] = g_topk_w[i];
    } else {
        int j = i - NTOK * TOPK;
        int s = j / NTOK, t = j % NTOK;
        int row = g_offsets[NE + s] + t;
        g_row_token[row] = t;
        g_row_w[row] = 1.0f;
    }
}

// ----- fp16 single-pass grouped FFN GEMM -----------------------------------
// PHASE1: hidden = silu(gather(x) @ W1)   K=DDIM -> g_hid (tiled fp16)
// PHASE2: out   += w_row * (hidden @ W2)  K=HDIM (atomicAdd)
template <bool PHASE1>
__global__ __launch_bounds__(256, 2)
void ffn_mma(float* __restrict__ out) {
    extern __shared__ char smem[];
    const int bm = blockIdx.x, bn = blockIdx.y;
    const int slot = g_tile_slot[bm];
    if (slot < 0) return;
    const int NC = PHASE1 ? NCH1 : NCH2;
    const int row0 = bm * TM, n0 = bn * TN;
    const int tid = threadIdx.x, wid = tid >> 5, lane = tid & 31;
    int* s_tok = (int*)(smem + OFF_TOK);
    float* s_w = (float*)(smem + OFF_W);
    if (tid < TM) {
        s_tok[tid] = g_row_token[row0 + tid];
        s_w[tid]   = g_row_w[row0 + tid];
    }
    __syncthreads();

    // ---- loader offsets: tile = 512 u4/chunk, 2 per thread ----
    int tDst[2];
#pragma unroll
    for (int i = 0; i < 2; i++) {
        int u = tid + i * 256;
        tDst[i] = (u >> 2) * PITCH + (u & 3) * 16;
    }

    const uint4* srcB = PHASE1
        ? (const uint4*)g_w1t + (size_t)(slot * NBN1 + bn) * NCH1 * 512
        : (const uint4*)g_w2t + (size_t)(slot * NBN2 + bn) * NCH2 * 512;
    const uint4* srcA2 = 0;
    const uint4* srcA1 = 0;
    const int sub = tid & 1;                 // phase1: which 2 u4 of the row chunk
    if (PHASE1) {
        int tok = s_tok[tid >> 1]; if (tok < 0) tok = 0;
        srcA1 = (const uint4*)(g_xc + (size_t)tok * NCH1 * 32) + sub * 2;
    } else {
        srcA2 = (const uint4*)g_hid + (size_t)bm * NCH2 * 512;
    }
    const int dA1 = (tid >> 1) * PITCH + sub * 32;

    const uint32_t sb = smem_u32(smem);
    const int warp_m = (wid >> 2) * 64;
    const int warp_n = (wid & 3) * 32;
    const int a_row = warp_m + (lane & 15);
    const int a_c8  = (lane >> 4) << 3;
    const int b_row = warp_n + (lane & 7) + ((lane >> 4) << 3);
    const int b_c8  = lane & 8;

    float acc[4][4][4];
#pragma unroll
    for (int i = 0; i < 4; i++)
#pragma unroll
        for (int j = 0; j < 4; j++)
#pragma unroll
            for (int k = 0; k < 4; k++) acc[i][j][k] = 0.0f;

    // -------- direct load of chunk 0 --------
    {
        if (PHASE1) {
            char* base = smem + AOF(0) + dA1;
            *(uint4*)(base)      = srcA1[0];
            *(uint4*)(base + 16) = srcA1[1];
        } else {
#pragma unroll
            for (int i = 0; i < 2; i++)
                *(uint4*)(smem + AOF(0) + tDst[i]) = srcA2[tid + i * 256];
        }
#pragma unroll
        for (int i = 0; i < 2; i++)
            *(uint4*)(smem + BOF(0) + tDst[i]) = srcB[tid + i * 256];
    }
    __syncthreads();

    // -------- main loop --------
    for (int c = 0; c < NC; c++) {
        const int buf = c & 1;
        const bool have = (c + 1 < NC);

        uint4 sA[2], sB[2];
        if (have) {
            if (PHASE1) {
                const uint4* p = srcA1 + (size_t)(c + 1) * 4;
                sA[0] = p[0]; sA[1] = p[1];
            } else {
                const uint4* p = srcA2 + (size_t)(c + 1) * 512;
                sA[0] = p[tid]; sA[1] = p[tid + 256];
            }
            const uint4* q = srcB + (size_t)(c + 1) * 512;
            sB[0] = q[tid]; sB[1] = q[tid + 256];
        }

        // ---- compute on buffer `buf` ----
        {
            const uint32_t ab = sb + AOF(buf);
            const uint32_t bb = sb + BOF(buf);
#pragma unroll
            for (int ks = 0; ks < 2; ks++) {
                const int kk = ks * 16;
                const uint32_t baddr = (uint32_t)(b_row * PITCH + (kk + b_c8) * 2);
                const uint32_t aaddr = (uint32_t)(a_row * PITCH + (kk + a_c8) * 2);
                uint32_t bh0[4], bh1[4];
                ldsm4(bh0, bb + baddr);
                ldsm4(bh1, bb + baddr + 16 * PITCH);
#pragma unroll
                for (int mi = 0; mi < 4; mi++) {
                    uint32_t af[4];
                    ldsm4(af, ab + aaddr + mi * 16 * PITCH);
                    mmaf16(acc[mi][0], af, bh0); mmaf16(acc[mi][1], af, bh0 + 2);
                    mmaf16(acc[mi][2], af, bh1); mmaf16(acc[mi][3], af, bh1 + 2);
                }
            }
        }

        // ---- STS staged chunk into other buffer ----
        if (have) {
            const int nb = (c + 1) & 1;
            if (PHASE1) {
                char* base = smem + AOF(nb) + dA1;
                *(uint4*)(base)      = sA[0];
                *(uint4*)(base + 16) = sA[1];
            } else {
                *(uint4*)(smem + AOF(nb) + tDst[0]) = sA[0];
                *(uint4*)(smem + AOF(nb) + tDst[1]) = sA[1];
            }
            *(uint4*)(smem + BOF(nb) + tDst[0]) = sB[0];
            *(uint4*)(smem + BOF(nb) + tDst[1]) = sB[1];
        }
        __syncthreads();
    }

    // -------- epilogue --------
    const int gid = lane >> 2, tig = lane & 3;
#pragma unroll
    for (int mi = 0; mi < 4; mi++) {
#pragma unroll
        for (int f = 0; f < 4; f++) {
            const int col = n0 + warp_n + f * 8 + tig * 2;
#pragma unroll
            for (int h = 0; h < 2; h++) {
                const int r = warp_m + mi * 16 + gid + h * 8;
                float v0 = acc[mi][f][2 * h];
                float v1 = acc[mi][f][2 * h + 1];
                if (PHASE1) {
                    v0 = v0 / (1.0f + __expf(-v0));
                    v1 = v1 / (1.0f + __expf(-v1));
                    // hidden tiled: [bm][col>>5][r][col&31] fp16
                    size_t base = ((size_t)bm * NCH2 + (col >> 5)) * ACH
                                  + (size_t)r * 32 + (col & 31);
                    *(uint32_t*)(g_hid + base) =
                        pkh(__float2half_rn(v0), __float2half_rn(v1));
                } else {
                    int tok = s_tok[r];
                    if (tok >= 0) {
                        float w = s_w[r];
                        float* op = out + (size_t)tok * DDIM + col;
                        atomicAdd(op,     w * v0);
                        atomicAdd(op + 1, w * v1);
                    }
                }
            }
        }
    }
}

// ---------------- launch ----------------
extern "C" void kernel_launch(void* const* d_in, const int* in_sizes, int n_in,
                              void* d_out, int out_size) {
    const float* x   = (const float*)d_in[0];
    const float* gw  = (const float*)d_in[1];
    const float* sw1 = (const float*)d_in[2];
    const float* sw2 = (const float*)d_in[3];
    const float* ew1 = (const float*)d_in[4];
    const float* ew2 = (const float*)d_in[5];
    float* out = (float*)d_out;

    cudaFuncSetAttribute(ffn_mma<true>,  cudaFuncAttributeMaxDynamicSharedMemorySize, SMEM_BYTES);
    cudaFuncSetAttribute(ffn_mma<false>, cudaFuncAttributeMaxDynamicSharedMemorySize, SMEM_BYTES);

    init_kernel<<<1024, 256>>>(out);
    router_kernel<<<NTOK, 128>>>(x, gw);
    schedule_kernel<<<1, 32>>>(out, (long long)out_size);
    scatter_kernel<<<(NTOK * (TOPK + NS) + 255) / 256, 256>>>();

    dim3 tb(32, 8);
    conv_w<1><<<dim3(DDIM / 32, HDIM / 32, NSLOT), tb>>>(ew1, sw1);
    conv_w<2><<<dim3(HDIM / 32, DDIM / 32, NSLOT), tb>>>(ew2, sw2);
    conv_x<<<(NTOK * DDIM / 4 + 255) / 256, 256>>>(x);

    dim3 g1(MAXTILESM, NBN1);   // 144 x 11
    dim3 g2(MAXTILESM, NBN2);   // 144 x 16
    ffn_mma<true ><<<g1, 256, SMEM_BYTES>>>(out);
    ffn_mma<false><<<g2, 256, SMEM_BYTES>>>(out);
}